// round 10
// baseline (speedup 1.0000x reference)
#include <cuda_runtime.h>

#define NN     5000
#define NE     160000
#define HID    64
#define BATCH  512
#define CAP    128            // ELL row capacity (Poisson(32); P(deg>128) ~ 1e-40)

// ---------------- scratch (device globals; zero-init at module load) ----------------
__device__ int      g_cnt[NN];              // degree; doubles as ELL slot counter; re-zeroed by k_final
__device__ float    g_msg1[NN * 4];         // layer-1 message sums; re-zeroed by k_final
__device__ __align__(16) int g_ell[NN * CAP];  // ELL adjacency: src lists per dst
__device__ __align__(16) float g_h1[NN * HID];
__device__ __align__(16) float g_mean[NN * HID];
__device__ __align__(16) float g_hp[5120 * HID];   // rows [5000,5120) stay zero forever
__device__ __align__(16) float g_tpT[HID * BATCH]; // transposed: [h][b]

union U64 { unsigned long long u; float2 f; };

__device__ __forceinline__ unsigned long long pack2(float a, float b) {
    unsigned long long r;
    asm("mov.b64 %0, {%1, %2};" : "=l"(r) : "f"(a), "f"(b));
    return r;
}

// per-block edge dtype detection: OR of 256 odd u32 words of this block's slice.
__device__ __forceinline__ int block_detect_i32(const unsigned* __restrict__ w, int e0) {
    __shared__ unsigned s_or[8];
    __shared__ int s_i32;
    int tid = threadIdx.x;
    unsigned odd = w[2 * (e0 + tid) + 1];
    odd = __reduce_or_sync(0xffffffffu, odd);
    if ((tid & 31) == 0) s_or[tid >> 5] = odd;
    __syncthreads();
    if (tid == 0) {
        unsigned a = 0;
#pragma unroll
        for (int i = 0; i < 8; i++) a |= s_or[i];
        s_i32 = (a != 0);
    }
    __syncthreads();
    return s_i32;
}

// -------- task MLP, one warp per batch, shuffle-based --------
__device__ __forceinline__ void do_task(int b, int lane, const float* __restrict__ tf,
                                        const float* __restrict__ Wt1, const float* __restrict__ bt1,
                                        const float* __restrict__ Wt2, const float* __restrict__ bt2,
                                        const float* __restrict__ Wc1, const float* __restrict__ bc1) {
    float4 f = *(const float4*)(tf + (size_t)b * 4);
    int o0 = lane, o1 = lane + 32;
    float a0 = bt1[o0] + Wt1[o0*4]*f.x + Wt1[o0*4+1]*f.y + Wt1[o0*4+2]*f.z + Wt1[o0*4+3]*f.w;
    float a1 = bt1[o1] + Wt1[o1*4]*f.x + Wt1[o1*4+1]*f.y + Wt1[o1*4+2]*f.z + Wt1[o1*4+3]*f.w;
    a0 = fmaxf(a0, 0.f); a1 = fmaxf(a1, 0.f);

    float c0 = bt2[o0], c1 = bt2[o1];
#pragma unroll
    for (int h = 0; h < 32; h++) {
        float v = __shfl_sync(0xffffffffu, a0, h);
        c0 += Wt2[o0*64 + h] * v;
        c1 += Wt2[o1*64 + h] * v;
    }
#pragma unroll
    for (int h = 0; h < 32; h++) {
        float v = __shfl_sync(0xffffffffu, a1, h);
        c0 += Wt2[o0*64 + 32 + h] * v;
        c1 += Wt2[o1*64 + 32 + h] * v;
    }
    float d0 = bc1[o0], d1 = bc1[o1];
#pragma unroll
    for (int h = 0; h < 32; h++) {
        float v = __shfl_sync(0xffffffffu, c0, h);
        d0 += Wc1[o0*128 + 64 + h] * v;
        d1 += Wc1[o1*128 + 64 + h] * v;
    }
#pragma unroll
    for (int h = 0; h < 32; h++) {
        float v = __shfl_sync(0xffffffffu, c1, h);
        d0 += Wc1[o0*128 + 96 + h] * v;
        d1 += Wc1[o1*128 + 96 + h] * v;
    }
    g_tpT[o0 * BATCH + b] = d0;
    g_tpT[o1 * BATCH + b] = d1;
}

// ---------------- 1) edge pass: ELL fill + degree + msg1 scatter; + task MLP ----------------
__global__ void __launch_bounds__(256) k_edge(
        const void* __restrict__ ei, const float* __restrict__ x,
        const float* __restrict__ tf,
        const float* __restrict__ Wt1, const float* __restrict__ bt1,
        const float* __restrict__ Wt2, const float* __restrict__ bt2,
        const float* __restrict__ Wc1, const float* __restrict__ bc1) {
    int bx = blockIdx.x;
    if (bx >= 625) {
        int b = (bx - 625) * 8 + (threadIdx.x >> 5);
        do_task(b, threadIdx.x & 31, tf, Wt1, bt1, Wt2, bt2, Wc1, bc1);
        return;
    }
    int e = bx * 256 + threadIdx.x;
    int i32 = block_detect_i32((const unsigned*)ei, bx * 256);
    int s, d;
    if (i32) { const int* p = (const int*)ei; s = p[e]; d = p[NE + e]; }
    else     { const long long* p = (const long long*)ei; s = (int)p[e]; d = (int)p[NE + e]; }
    int slot = atomicAdd(&g_cnt[d], 1);           // histogram AND unique ELL slot
    if (slot < CAP) g_ell[d * CAP + slot] = s;
    float4 xv = *(const float4*)(x + (size_t)s * 4);
    atomicAdd(&g_msg1[d*4 + 0], xv.x);
    atomicAdd(&g_msg1[d*4 + 1], xv.y);
    atomicAdd(&g_msg1[d*4 + 2], xv.z);
    atomicAdd(&g_msg1[d*4 + 3], xv.w);
}

// ---------------- 2) layer-1 node update ----------------
__global__ void __launch_bounds__(256) k_node1(
        const float* __restrict__ x,
        const float* __restrict__ Wl1, const float* __restrict__ bl1,
        const float* __restrict__ Wr1) {
    int t = blockIdx.x * 256 + threadIdx.x;    // < 320000
    int n = t >> 6, o = t & 63;
    float invd = 1.f / fmaxf((float)g_cnt[n], 1.f);
    float acc = bl1[o];
#pragma unroll
    for (int f = 0; f < 4; f++)
        acc += Wl1[o*4 + f] * (g_msg1[n*4 + f] * invd) + Wr1[o*4 + f] * x[n*4 + f];
    g_h1[t] = fmaxf(acc, 0.f);
}

// ---------------- 3) mean gather: warp per node, int4 edge loads, 8 chains ----------------
__global__ void __launch_bounds__(256) k_gather2() {
    int n    = blockIdx.x * 8 + (threadIdx.x >> 5);
    int lane = threadIdx.x & 31;
    int deg  = min(g_cnt[n], CAP);
    const int4* row = (const int4*)(g_ell + n * CAP);
    float a0 = 0.f, a1 = 0.f, b0 = 0.f, b1 = 0.f;
    float c0 = 0.f, c1 = 0.f, d0 = 0.f, d1 = 0.f;
    int nq = deg >> 2;
    for (int q = 0; q < nq; q++) {
        int4 s4 = row[q];
        a0 += __ldg(&g_h1[s4.x*64 + lane]);
        a1 += __ldg(&g_h1[s4.x*64 + 32 + lane]);
        b0 += __ldg(&g_h1[s4.y*64 + lane]);
        b1 += __ldg(&g_h1[s4.y*64 + 32 + lane]);
        c0 += __ldg(&g_h1[s4.z*64 + lane]);
        c1 += __ldg(&g_h1[s4.z*64 + 32 + lane]);
        d0 += __ldg(&g_h1[s4.w*64 + lane]);
        d1 += __ldg(&g_h1[s4.w*64 + 32 + lane]);
    }
    for (int e = nq * 4; e < deg; e++) {
        int s = g_ell[n * CAP + e];
        a0 += __ldg(&g_h1[s*64 + lane]);
        a1 += __ldg(&g_h1[s*64 + 32 + lane]);
    }
    float invd = 1.f / fmaxf((float)deg, 1.f);
    g_mean[n*64 + lane]      = (a0 + b0 + c0 + d0) * invd;
    g_mean[n*64 + 32 + lane] = (a1 + b1 + c1 + d1) * invd;
}

// ---------------- 4) GEMM: h2 = relu(Wl2@mean+bl2+Wr2@h1); hp = h2@Wc1h^T  (PROFILED) ----------------
// 16 nodes x 64 outs per block, 256 threads (1 node x 4 outs each), grid 313 -> 2 blocks/SM.
#define MM_NODES 16
#define MM_GRID  ((NN + MM_NODES - 1) / MM_NODES)    // 313
#define WS 68
#define MS 17
#define SM_BYTES ((3*64*WS + 2*64*MS) * 4)           // 60928 B
__global__ void __launch_bounds__(256) k_l2mm(const float* __restrict__ Wl2,
                                              const float* __restrict__ bl2,
                                              const float* __restrict__ Wr2,
                                              const float* __restrict__ Wc1) {
    extern __shared__ float sm[];
    float* sWl   = sm;                   // [k*WS + o]
    float* sWr   = sm + 64*WS;
    float* sWc   = sm + 2*64*WS;
    float* sMean = sm + 3*64*WS;         // [k*MS + nl]; later aliased as sH2
    float* sX    = sMean + 64*MS;
    int tid = threadIdx.x;
    int n0 = blockIdx.x * MM_NODES;

    for (int idx = tid; idx < 4096; idx += 256) {
        int o = idx >> 6, k = idx & 63;
        sWl[k*WS + o] = Wl2[idx];
        sWr[k*WS + o] = Wr2[idx];
        sWc[k*WS + o] = Wc1[o*128 + k];  // h-part of Wc1
    }
    for (int idx = tid; idx < 1024; idx += 256) {
        int nl = idx >> 6, k = idx & 63;
        int n = n0 + nl;
        bool ok = (n < NN);
        sMean[k*MS + nl] = ok ? g_mean[n*64 + k] : 0.f;
        sX[k*MS + nl]    = ok ? g_h1[n*64 + k]   : 0.f;
    }
    __syncthreads();

    int tx = tid & 15, nl = tid >> 4;    // tx: out group, nl: node 0..15
    int o0 = tx * 4;

    float4 acc = *(const float4*)(bl2 + o0);
#pragma unroll
    for (int k = 0; k < 64; k++) {
        float m = sMean[k*MS + nl];
        float xv = sX[k*MS + nl];
        float4 wl = *(const float4*)(sWl + k*WS + o0);
        float4 wr = *(const float4*)(sWr + k*WS + o0);
        acc.x += m*wl.x + xv*wr.x; acc.y += m*wl.y + xv*wr.y;
        acc.z += m*wl.z + xv*wr.z; acc.w += m*wl.w + xv*wr.w;
    }
    acc.x = fmaxf(acc.x, 0.f); acc.y = fmaxf(acc.y, 0.f);
    acc.z = fmaxf(acc.z, 0.f); acc.w = fmaxf(acc.w, 0.f);
    __syncthreads();

    float* sH2 = sMean;
    sH2[(o0+0)*MS + nl] = acc.x; sH2[(o0+1)*MS + nl] = acc.y;
    sH2[(o0+2)*MS + nl] = acc.z; sH2[(o0+3)*MS + nl] = acc.w;
    __syncthreads();

    float4 p = make_float4(0.f, 0.f, 0.f, 0.f);
#pragma unroll
    for (int k = 0; k < 64; k++) {
        float h0 = sH2[k*MS + nl];
        float4 wc = *(const float4*)(sWc + k*WS + o0);
        p.x += h0*wc.x; p.y += h0*wc.y; p.z += h0*wc.z; p.w += h0*wc.w;
    }
    int n = n0 + nl;
    if (n < NN) *(float4*)(g_hp + (size_t)n * 64 + o0) = p;
}

// ---------------- 5) final scores + re-zero side jobs ----------------
// Tile 128 nodes x 64 batches, 256 threads, grid (40,8).
#define FIN_SMEM (64*129*4 + 64*64*4 + 64*8)
__global__ void __launch_bounds__(256) k_final(const float* __restrict__ Wc2,
                                               const float* __restrict__ bc2,
                                               float* __restrict__ out) {
    extern __shared__ float smf[];
    float* s_hp = smf;                         // [h][r], stride 129
    float* s_tp = smf + 64 * 129;              // [h][b], 64 wide
    unsigned long long* s_w2 = (unsigned long long*)(smf + 64 * 129 + 64 * 64);
    int tid = threadIdx.x;

    // side job: re-zero accumulators (blocks 0..97 x 256 = 25088 >= 25000)
    int bid = blockIdx.y * gridDim.x + blockIdx.x;
    if (bid < 98) {
        int i = bid * 256 + tid;
        if (i < NN)     g_cnt[i]  = 0;
        if (i < NN * 4) g_msg1[i] = 0.f;
    }

    int n0 = blockIdx.x * 128, b0 = blockIdx.y * 64;
    for (int idx = tid; idx < 8192; idx += 256) {
        int r = idx >> 6, h = idx & 63;
        s_hp[h*129 + r] = g_hp[(size_t)(n0 + r) * 64 + h];
    }
    for (int idx = tid; idx < 4096; idx += 256) {
        int h = idx >> 6, b = idx & 63;
        s_tp[h*64 + b] = g_tpT[h * BATCH + b0 + b];
    }
    if (tid < 64) { float w = Wc2[tid]; s_w2[tid] = pack2(w, w); }
    __syncthreads();

    int nla = tid & 63, q = tid >> 6;          // q in {0..3}: 16 batches each
    int nlb = nla + 64;
    U64 accA[8], accB[8];
#pragma unroll
    for (int p = 0; p < 8; p++) { accA[p].u = 0ull; accB[p].u = 0ull; }

#pragma unroll 4
    for (int h = 0; h < 64; h++) {
        float hva = s_hp[h*129 + nla];
        float hvb = s_hp[h*129 + nlb];
        unsigned long long ha = pack2(hva, hva);
        unsigned long long hb = pack2(hvb, hvb);
        unsigned long long w2 = s_w2[h];
        const unsigned long long* tp = (const unsigned long long*)(s_tp + h*64 + q*16);
#pragma unroll
        for (int p = 0; p < 8; p++) {
            unsigned long long t2 = tp[p];
            U64 a, b;
            asm("add.rn.f32x2 %0, %1, %2;" : "=l"(a.u) : "l"(t2), "l"(ha));
            asm("add.rn.f32x2 %0, %1, %2;" : "=l"(b.u) : "l"(t2), "l"(hb));
            a.f.x = fmaxf(a.f.x, 0.f); a.f.y = fmaxf(a.f.y, 0.f);
            b.f.x = fmaxf(b.f.x, 0.f); b.f.y = fmaxf(b.f.y, 0.f);
            asm("fma.rn.f32x2 %0, %1, %2, %0;" : "+l"(accA[p].u) : "l"(a.u), "l"(w2));
            asm("fma.rn.f32x2 %0, %1, %2, %0;" : "+l"(accB[p].u) : "l"(b.u), "l"(w2));
        }
    }

    float bias = bc2[0];
    int na = n0 + nla, nb = n0 + nlb;
    if (na < NN) {
#pragma unroll
        for (int p = 0; p < 8; p++) {
            int b = b0 + q*16 + 2*p;
            out[(size_t)b       * NN + na] = accA[p].f.x + bias;
            out[(size_t)(b + 1) * NN + na] = accA[p].f.y + bias;
        }
    }
    if (nb < NN) {
#pragma unroll
        for (int p = 0; p < 8; p++) {
            int b = b0 + q*16 + 2*p;
            out[(size_t)b       * NN + nb] = accB[p].f.x + bias;
            out[(size_t)(b + 1) * NN + nb] = accB[p].f.y + bias;
        }
    }
}

// ---------------- launch ----------------
extern "C" void kernel_launch(void* const* d_in, const int* in_sizes, int n_in,
                              void* d_out, int out_size) {
    const float* x   = (const float*)d_in[0];
    const void*  ei  = d_in[1];
    const float* tf  = (const float*)d_in[2];
    const float* Wl1 = (const float*)d_in[3];
    const float* bl1 = (const float*)d_in[4];
    const float* Wr1 = (const float*)d_in[5];
    const float* Wl2 = (const float*)d_in[6];
    const float* bl2 = (const float*)d_in[7];
    const float* Wr2 = (const float*)d_in[8];
    const float* Wt1 = (const float*)d_in[9];
    const float* bt1 = (const float*)d_in[10];
    const float* Wt2 = (const float*)d_in[11];
    const float* bt2 = (const float*)d_in[12];
    const float* Wc1 = (const float*)d_in[13];
    const float* bc1 = (const float*)d_in[14];
    const float* Wc2 = (const float*)d_in[15];
    const float* bc2 = (const float*)d_in[16];
    float* out = (float*)d_out;

    static bool attr_set = false;
    if (!attr_set) {
        cudaFuncSetAttribute(k_l2mm,  cudaFuncAttributeMaxDynamicSharedMemorySize, SM_BYTES);
        cudaFuncSetAttribute(k_final, cudaFuncAttributeMaxDynamicSharedMemorySize, FIN_SMEM);
        attr_set = true;
    }

    k_edge   <<<689, 256>>>(ei, x, tf, Wt1, bt1, Wt2, bt2, Wc1, bc1);
    k_node1  <<<1250, 256>>>(x, Wl1, bl1, Wr1);
    k_gather2<<<625, 256>>>();
    k_l2mm   <<<MM_GRID, 256, SM_BYTES>>>(Wl2, bl2, Wr2, Wc1);   // 4th -> profiled
    k_final  <<<dim3(40, 8), 256, FIN_SMEM>>>(Wc2, bc2, out);
}

// round 11
// speedup vs baseline: 1.0676x; 1.0676x over previous
#include <cuda_runtime.h>
#include <cuda_fp16.h>

#define NN     5000
#define NE     160000
#define HID    64
#define BATCH  512
#define CAP    128            // ELL row capacity (Poisson(32); P(deg>128) ~ 1e-40)

// ---------------- scratch (device globals; zero-init at module load) ----------------
__device__ int      g_cnt[NN];              // degree / ELL slot counter; re-zeroed by k_final
__device__ __align__(16) int g_ell[NN * CAP];
__device__ __align__(16) float   g_h1 [NN * HID];    // fp32 h1 (own-feature GEMM term)
__device__ __align__(8)  __half2 g_h1h[NN * 32];     // fp16 mirror (gather traffic)
__device__ __align__(16) float g_mean[NN * HID];
__device__ __align__(16) float g_hp[5120 * HID];     // rows [5000,5120) stay zero forever
__device__ __align__(16) float g_tpT[HID * BATCH];   // transposed: [h][b]

union U64 { unsigned long long u; float2 f; };

__device__ __forceinline__ unsigned long long pack2(float a, float b) {
    unsigned long long r;
    asm("mov.b64 %0, {%1, %2};" : "=l"(r) : "f"(a), "f"(b));
    return r;
}

// per-block edge dtype detection: OR of 256 odd u32 words of this block's slice.
__device__ __forceinline__ int block_detect_i32(const unsigned* __restrict__ w, int e0) {
    __shared__ unsigned s_or[8];
    __shared__ int s_i32;
    int tid = threadIdx.x;
    unsigned odd = w[2 * (e0 + tid) + 1];
    odd = __reduce_or_sync(0xffffffffu, odd);
    if ((tid & 31) == 0) s_or[tid >> 5] = odd;
    __syncthreads();
    if (tid == 0) {
        unsigned a = 0;
#pragma unroll
        for (int i = 0; i < 8; i++) a |= s_or[i];
        s_i32 = (a != 0);
    }
    __syncthreads();
    return s_i32;
}

// -------- task MLP, one warp per batch, shuffle-based --------
__device__ __forceinline__ void do_task(int b, int lane, const float* __restrict__ tf,
                                        const float* __restrict__ Wt1, const float* __restrict__ bt1,
                                        const float* __restrict__ Wt2, const float* __restrict__ bt2,
                                        const float* __restrict__ Wc1, const float* __restrict__ bc1) {
    float4 f = *(const float4*)(tf + (size_t)b * 4);
    int o0 = lane, o1 = lane + 32;
    float a0 = bt1[o0] + Wt1[o0*4]*f.x + Wt1[o0*4+1]*f.y + Wt1[o0*4+2]*f.z + Wt1[o0*4+3]*f.w;
    float a1 = bt1[o1] + Wt1[o1*4]*f.x + Wt1[o1*4+1]*f.y + Wt1[o1*4+2]*f.z + Wt1[o1*4+3]*f.w;
    a0 = fmaxf(a0, 0.f); a1 = fmaxf(a1, 0.f);

    float c0 = bt2[o0], c1 = bt2[o1];
#pragma unroll
    for (int h = 0; h < 32; h++) {
        float v = __shfl_sync(0xffffffffu, a0, h);
        c0 += Wt2[o0*64 + h] * v;
        c1 += Wt2[o1*64 + h] * v;
    }
#pragma unroll
    for (int h = 0; h < 32; h++) {
        float v = __shfl_sync(0xffffffffu, a1, h);
        c0 += Wt2[o0*64 + 32 + h] * v;
        c1 += Wt2[o1*64 + 32 + h] * v;
    }
    float d0 = bc1[o0], d1 = bc1[o1];
#pragma unroll
    for (int h = 0; h < 32; h++) {
        float v = __shfl_sync(0xffffffffu, c0, h);
        d0 += Wc1[o0*128 + 64 + h] * v;
        d1 += Wc1[o1*128 + 64 + h] * v;
    }
#pragma unroll
    for (int h = 0; h < 32; h++) {
        float v = __shfl_sync(0xffffffffu, c1, h);
        d0 += Wc1[o0*128 + 96 + h] * v;
        d1 += Wc1[o1*128 + 96 + h] * v;
    }
    g_tpT[o0 * BATCH + b] = d0;
    g_tpT[o1 * BATCH + b] = d1;
}

// ---------------- 1) edge pass: ELL fill + degree; + task MLP (lean: no float atomics) ----------------
__global__ void __launch_bounds__(256) k_edge(
        const void* __restrict__ ei, const float* __restrict__ tf,
        const float* __restrict__ Wt1, const float* __restrict__ bt1,
        const float* __restrict__ Wt2, const float* __restrict__ bt2,
        const float* __restrict__ Wc1, const float* __restrict__ bc1) {
    int bx = blockIdx.x;
    if (bx >= 625) {
        int b = (bx - 625) * 8 + (threadIdx.x >> 5);
        do_task(b, threadIdx.x & 31, tf, Wt1, bt1, Wt2, bt2, Wc1, bc1);
        return;
    }
    int e = bx * 256 + threadIdx.x;
    int i32 = block_detect_i32((const unsigned*)ei, bx * 256);
    int s, d;
    if (i32) { const int* p = (const int*)ei; s = p[e]; d = p[NE + e]; }
    else     { const long long* p = (const long long*)ei; s = (int)p[e]; d = (int)p[NE + e]; }
    int slot = atomicAdd(&g_cnt[d], 1);
    if (slot < CAP) g_ell[d * CAP + slot] = s;
}

// ---------------- 2) layer-1: warp per node, ELL gather of x, fused matvec ----------------
__global__ void __launch_bounds__(256) k_node1(
        const float* __restrict__ x,
        const float* __restrict__ Wl1, const float* __restrict__ bl1,
        const float* __restrict__ Wr1) {
    int n    = blockIdx.x * 8 + (threadIdx.x >> 5);
    int lane = threadIdx.x & 31;
    int deg  = min(g_cnt[n], CAP);
    const int* row = g_ell + n * CAP;
    float4 a = make_float4(0.f, 0.f, 0.f, 0.f);
    for (int e = lane; e < deg; e += 32) {
        float4 xv = __ldg((const float4*)(x + (size_t)row[e] * 4));
        a.x += xv.x; a.y += xv.y; a.z += xv.z; a.w += xv.w;
    }
#pragma unroll
    for (int off = 16; off; off >>= 1) {
        a.x += __shfl_xor_sync(0xffffffffu, a.x, off);
        a.y += __shfl_xor_sync(0xffffffffu, a.y, off);
        a.z += __shfl_xor_sync(0xffffffffu, a.z, off);
        a.w += __shfl_xor_sync(0xffffffffu, a.w, off);
    }
    float invd = 1.f / fmaxf((float)deg, 1.f);
    float m0 = a.x*invd, m1 = a.y*invd, m2 = a.z*invd, m3 = a.w*invd;
    float4 xn = __ldg((const float4*)(x + (size_t)n * 4));
    // lane computes outs 2*lane, 2*lane+1 (adjacent -> half2 pack)
    int oa = 2 * lane, ob = 2 * lane + 1;
    float va = bl1[oa]
             + Wl1[oa*4]*m0 + Wl1[oa*4+1]*m1 + Wl1[oa*4+2]*m2 + Wl1[oa*4+3]*m3
             + Wr1[oa*4]*xn.x + Wr1[oa*4+1]*xn.y + Wr1[oa*4+2]*xn.z + Wr1[oa*4+3]*xn.w;
    float vb = bl1[ob]
             + Wl1[ob*4]*m0 + Wl1[ob*4+1]*m1 + Wl1[ob*4+2]*m2 + Wl1[ob*4+3]*m3
             + Wr1[ob*4]*xn.x + Wr1[ob*4+1]*xn.y + Wr1[ob*4+2]*xn.z + Wr1[ob*4+3]*xn.w;
    va = fmaxf(va, 0.f); vb = fmaxf(vb, 0.f);
    *(float2*)(g_h1 + (size_t)n * 64 + oa) = make_float2(va, vb);
    g_h1h[n * 32 + lane] = __floats2half2_rn(va, vb);
}

// ---------------- 3) mean gather over fp16 h1: warp per node, int4 edges, 4 chains ----------------
__global__ void __launch_bounds__(256) k_gather2() {
    int n    = blockIdx.x * 8 + (threadIdx.x >> 5);
    int lane = threadIdx.x & 31;
    int deg  = min(g_cnt[n], CAP);
    const int4* row = (const int4*)(g_ell + n * CAP);
    float2 a = make_float2(0.f, 0.f), b = make_float2(0.f, 0.f);
    float2 c = make_float2(0.f, 0.f), d = make_float2(0.f, 0.f);
    int nq = deg >> 2;
    for (int q = 0; q < nq; q++) {
        int4 s4 = row[q];
        float2 va = __half22float2(__ldg(&g_h1h[s4.x * 32 + lane]));
        float2 vb = __half22float2(__ldg(&g_h1h[s4.y * 32 + lane]));
        float2 vc = __half22float2(__ldg(&g_h1h[s4.z * 32 + lane]));
        float2 vd = __half22float2(__ldg(&g_h1h[s4.w * 32 + lane]));
        a.x += va.x; a.y += va.y;
        b.x += vb.x; b.y += vb.y;
        c.x += vc.x; c.y += vc.y;
        d.x += vd.x; d.y += vd.y;
    }
    for (int e = nq * 4; e < deg; e++) {
        int s = g_ell[n * CAP + e];
        float2 v = __half22float2(__ldg(&g_h1h[s * 32 + lane]));
        a.x += v.x; a.y += v.y;
    }
    float invd = 1.f / fmaxf((float)deg, 1.f);
    float2 m;
    m.x = (a.x + b.x + c.x + d.x) * invd;
    m.y = (a.y + b.y + c.y + d.y) * invd;
    *(float2*)(g_mean + (size_t)n * 64 + 2 * lane) = m;
}

// ---------------- 4) GEMM: h2 = relu(Wl2@mean+bl2+Wr2@h1); hp = h2@Wc1h^T  (PROFILED) ----------------
// 512 threads = 16 nodes x 32 out-pairs (2 outs/thread). Grid 313 -> 32 warps/SM.
#define MM_NODES 16
#define MM_GRID  ((NN + MM_NODES - 1) / MM_NODES)    // 313
#define WS2 66                                       // float2-aligned, low-conflict
#define MS2 17
#define SM_BYTES ((3*64*WS2 + 2*64*MS2) * 4)         // 59392 B
__global__ void __launch_bounds__(512) k_l2mm(const float* __restrict__ Wl2,
                                              const float* __restrict__ bl2,
                                              const float* __restrict__ Wr2,
                                              const float* __restrict__ Wc1) {
    extern __shared__ float sm[];
    float* sWl   = sm;                   // [k*WS2 + o]
    float* sWr   = sm + 64*WS2;
    float* sWc   = sm + 2*64*WS2;
    float* sMean = sm + 3*64*WS2;        // [k*MS2 + nl]; aliased as sH2 later
    float* sX    = sMean + 64*MS2;
    int tid = threadIdx.x;
    int n0 = blockIdx.x * MM_NODES;

    for (int idx = tid; idx < 4096; idx += 512) {
        int o = idx >> 6, k = idx & 63;
        sWl[k*WS2 + o] = Wl2[idx];
        sWr[k*WS2 + o] = Wr2[idx];
        sWc[k*WS2 + o] = Wc1[o*128 + k];  // h-part of Wc1
    }
    for (int idx = tid; idx < 1024; idx += 512) {
        int nl = idx >> 6, k = idx & 63;
        int n = n0 + nl;
        bool ok = (n < NN);
        sMean[k*MS2 + nl] = ok ? g_mean[n*64 + k] : 0.f;
        sX[k*MS2 + nl]    = ok ? g_h1[n*64 + k]   : 0.f;
    }
    __syncthreads();

    int op = tid & 31, nl = tid >> 5;    // op: out-pair 0..31, nl: node 0..15
    int o0 = op * 2;

    float2 acc = *(const float2*)(bl2 + o0);
#pragma unroll
    for (int k = 0; k < 64; k++) {
        float m  = sMean[k*MS2 + nl];
        float xv = sX[k*MS2 + nl];
        float2 wl = *(const float2*)(sWl + k*WS2 + o0);
        float2 wr = *(const float2*)(sWr + k*WS2 + o0);
        acc.x += m*wl.x + xv*wr.x;
        acc.y += m*wl.y + xv*wr.y;
    }
    acc.x = fmaxf(acc.x, 0.f); acc.y = fmaxf(acc.y, 0.f);
    __syncthreads();

    float* sH2 = sMean;
    sH2[(o0+0)*MS2 + nl] = acc.x;
    sH2[(o0+1)*MS2 + nl] = acc.y;
    __syncthreads();

    float2 p = make_float2(0.f, 0.f);
#pragma unroll
    for (int k = 0; k < 64; k++) {
        float h0 = sH2[k*MS2 + nl];
        float2 wc = *(const float2*)(sWc + k*WS2 + o0);
        p.x += h0*wc.x;
        p.y += h0*wc.y;
    }
    int n = n0 + nl;
    if (n < NN) *(float2*)(g_hp + (size_t)n * 64 + o0) = p;
}

// ---------------- 5) final scores + re-zero side job ----------------
// Tile 128 nodes x 64 batches, 256 threads, grid (40,8).
#define FIN_SMEM (64*129*4 + 64*64*4 + 64*8)
__global__ void __launch_bounds__(256) k_final(const float* __restrict__ Wc2,
                                               const float* __restrict__ bc2,
                                               float* __restrict__ out) {
    extern __shared__ float smf[];
    float* s_hp = smf;                         // [h][r], stride 129
    float* s_tp = smf + 64 * 129;              // [h][b], 64 wide
    unsigned long long* s_w2 = (unsigned long long*)(smf + 64 * 129 + 64 * 64);
    int tid = threadIdx.x;

    // side job: re-zero degree counters (blocks 0..19 x 256 = 5120 >= 5000)
    int bid = blockIdx.y * gridDim.x + blockIdx.x;
    if (bid < 20) {
        int i = bid * 256 + tid;
        if (i < NN) g_cnt[i] = 0;
    }

    int n0 = blockIdx.x * 128, b0 = blockIdx.y * 64;
    for (int idx = tid; idx < 8192; idx += 256) {
        int r = idx >> 6, h = idx & 63;
        s_hp[h*129 + r] = g_hp[(size_t)(n0 + r) * 64 + h];
    }
    for (int idx = tid; idx < 4096; idx += 256) {
        int h = idx >> 6, b = idx & 63;
        s_tp[h*64 + b] = g_tpT[h * BATCH + b0 + b];
    }
    if (tid < 64) { float w = Wc2[tid]; s_w2[tid] = pack2(w, w); }
    __syncthreads();

    int nla = tid & 63, q = tid >> 6;          // q in {0..3}: 16 batches each
    int nlb = nla + 64;
    U64 accA[8], accB[8];
#pragma unroll
    for (int p = 0; p < 8; p++) { accA[p].u = 0ull; accB[p].u = 0ull; }

#pragma unroll 4
    for (int h = 0; h < 64; h++) {
        float hva = s_hp[h*129 + nla];
        float hvb = s_hp[h*129 + nlb];
        unsigned long long ha = pack2(hva, hva);
        unsigned long long hb = pack2(hvb, hvb);
        unsigned long long w2 = s_w2[h];
        const unsigned long long* tp = (const unsigned long long*)(s_tp + h*64 + q*16);
#pragma unroll
        for (int p = 0; p < 8; p++) {
            unsigned long long t2 = tp[p];
            U64 a, b;
            asm("add.rn.f32x2 %0, %1, %2;" : "=l"(a.u) : "l"(t2), "l"(ha));
            asm("add.rn.f32x2 %0, %1, %2;" : "=l"(b.u) : "l"(t2), "l"(hb));
            a.f.x = fmaxf(a.f.x, 0.f); a.f.y = fmaxf(a.f.y, 0.f);
            b.f.x = fmaxf(b.f.x, 0.f); b.f.y = fmaxf(b.f.y, 0.f);
            asm("fma.rn.f32x2 %0, %1, %2, %0;" : "+l"(accA[p].u) : "l"(a.u), "l"(w2));
            asm("fma.rn.f32x2 %0, %1, %2, %0;" : "+l"(accB[p].u) : "l"(b.u), "l"(w2));
        }
    }

    float bias = bc2[0];
    int na = n0 + nla, nb = n0 + nlb;
    if (na < NN) {
#pragma unroll
        for (int p = 0; p < 8; p++) {
            int b = b0 + q*16 + 2*p;
            out[(size_t)b       * NN + na] = accA[p].f.x + bias;
            out[(size_t)(b + 1) * NN + na] = accA[p].f.y + bias;
        }
    }
    if (nb < NN) {
#pragma unroll
        for (int p = 0; p < 8; p++) {
            int b = b0 + q*16 + 2*p;
            out[(size_t)b       * NN + nb] = accB[p].f.x + bias;
            out[(size_t)(b + 1) * NN + nb] = accB[p].f.y + bias;
        }
    }
}

// ---------------- launch ----------------
extern "C" void kernel_launch(void* const* d_in, const int* in_sizes, int n_in,
                              void* d_out, int out_size) {
    const float* x   = (const float*)d_in[0];
    const void*  ei  = d_in[1];
    const float* tf  = (const float*)d_in[2];
    const float* Wl1 = (const float*)d_in[3];
    const float* bl1 = (const float*)d_in[4];
    const float* Wr1 = (const float*)d_in[5];
    const float* Wl2 = (const float*)d_in[6];
    const float* bl2 = (const float*)d_in[7];
    const float* Wr2 = (const float*)d_in[8];
    const float* Wt1 = (const float*)d_in[9];
    const float* bt1 = (const float*)d_in[10];
    const float* Wt2 = (const float*)d_in[11];
    const float* bt2 = (const float*)d_in[12];
    const float* Wc1 = (const float*)d_in[13];
    const float* bc1 = (const float*)d_in[14];
    const float* Wc2 = (const float*)d_in[15];
    const float* bc2 = (const float*)d_in[16];
    float* out = (float*)d_out;

    static bool attr_set = false;
    if (!attr_set) {
        cudaFuncSetAttribute(k_l2mm,  cudaFuncAttributeMaxDynamicSharedMemorySize, SM_BYTES);
        cudaFuncSetAttribute(k_final, cudaFuncAttributeMaxDynamicSharedMemorySize, FIN_SMEM);
        attr_set = true;
    }

    k_edge   <<<689, 256>>>(ei, tf, Wt1, bt1, Wt2, bt2, Wc1, bc1);
    k_node1  <<<625, 256>>>(x, Wl1, bl1, Wr1);
    k_gather2<<<625, 256>>>();
    k_l2mm   <<<MM_GRID, 512, SM_BYTES>>>(Wl2, bl2, Wr2, Wc1);   // 4th -> profiled
    k_final  <<<dim3(40, 8), 256, FIN_SMEM>>>(Wc2, bc2, out);
}

// round 12
// speedup vs baseline: 1.0915x; 1.0225x over previous
#include <cuda_runtime.h>
#include <cuda_fp16.h>

#define NN     5000
#define NE     160000
#define HID    64
#define BATCH  512
#define CAP    128            // ELL row capacity (Poisson(32); P(deg>128) ~ 1e-40)

// ---------------- scratch (device globals; zero-init at module load) ----------------
__device__ int      g_cnt[NN];              // degree / ELL slot counter; re-zeroed by k_final
__device__ __align__(16) int g_ell[NN * CAP];
__device__ __align__(16) float   g_h1 [NN * HID];    // fp32 h1 (own-feature GEMM term)
__device__ __align__(8)  __half2 g_h1h[NN * 32];     // fp16 mirror (gather traffic)
__device__ __align__(16) float g_mean[NN * HID];
__device__ __align__(16) float g_hp[5120 * HID];     // rows [5000,5120) stay zero forever
__device__ __align__(16) float g_tpT[HID * BATCH];   // transposed: [h][b]

union U64 { unsigned long long u; float2 f; };

__device__ __forceinline__ unsigned long long pack2(float a, float b) {
    unsigned long long r;
    asm("mov.b64 %0, {%1, %2};" : "=l"(r) : "f"(a), "f"(b));
    return r;
}

// per-block edge dtype detection: OR of 256 odd u32 words of this block's slice.
__device__ __forceinline__ int block_detect_i32(const unsigned* __restrict__ w, int e0) {
    __shared__ unsigned s_or[8];
    __shared__ int s_i32;
    int tid = threadIdx.x;
    unsigned odd = w[2 * (e0 + tid) + 1];
    odd = __reduce_or_sync(0xffffffffu, odd);
    if ((tid & 31) == 0) s_or[tid >> 5] = odd;
    __syncthreads();
    if (tid == 0) {
        unsigned a = 0;
#pragma unroll
        for (int i = 0; i < 8; i++) a |= s_or[i];
        s_i32 = (a != 0);
    }
    __syncthreads();
    return s_i32;
}

// -------- task MLP, one warp per batch, shuffle-based --------
__device__ __forceinline__ void do_task(int b, int lane, const float* __restrict__ tf,
                                        const float* __restrict__ Wt1, const float* __restrict__ bt1,
                                        const float* __restrict__ Wt2, const float* __restrict__ bt2,
                                        const float* __restrict__ Wc1, const float* __restrict__ bc1) {
    float4 f = *(const float4*)(tf + (size_t)b * 4);
    int o0 = lane, o1 = lane + 32;
    float a0 = bt1[o0] + Wt1[o0*4]*f.x + Wt1[o0*4+1]*f.y + Wt1[o0*4+2]*f.z + Wt1[o0*4+3]*f.w;
    float a1 = bt1[o1] + Wt1[o1*4]*f.x + Wt1[o1*4+1]*f.y + Wt1[o1*4+2]*f.z + Wt1[o1*4+3]*f.w;
    a0 = fmaxf(a0, 0.f); a1 = fmaxf(a1, 0.f);

    float c0 = bt2[o0], c1 = bt2[o1];
#pragma unroll
    for (int h = 0; h < 32; h++) {
        float v = __shfl_sync(0xffffffffu, a0, h);
        c0 += Wt2[o0*64 + h] * v;
        c1 += Wt2[o1*64 + h] * v;
    }
#pragma unroll
    for (int h = 0; h < 32; h++) {
        float v = __shfl_sync(0xffffffffu, a1, h);
        c0 += Wt2[o0*64 + 32 + h] * v;
        c1 += Wt2[o1*64 + 32 + h] * v;
    }
    float d0 = bc1[o0], d1 = bc1[o1];
#pragma unroll
    for (int h = 0; h < 32; h++) {
        float v = __shfl_sync(0xffffffffu, c0, h);
        d0 += Wc1[o0*128 + 64 + h] * v;
        d1 += Wc1[o1*128 + 64 + h] * v;
    }
#pragma unroll
    for (int h = 0; h < 32; h++) {
        float v = __shfl_sync(0xffffffffu, c1, h);
        d0 += Wc1[o0*128 + 96 + h] * v;
        d1 += Wc1[o1*128 + 96 + h] * v;
    }
    g_tpT[o0 * BATCH + b] = d0;
    g_tpT[o1 * BATCH + b] = d1;
}

// ---------------- 1) edge pass: ELL fill + degree; + task MLP ----------------
__global__ void __launch_bounds__(256) k_edge(
        const void* __restrict__ ei, const float* __restrict__ tf,
        const float* __restrict__ Wt1, const float* __restrict__ bt1,
        const float* __restrict__ Wt2, const float* __restrict__ bt2,
        const float* __restrict__ Wc1, const float* __restrict__ bc1) {
    int bx = blockIdx.x;
    if (bx >= 625) {
        int b = (bx - 625) * 8 + (threadIdx.x >> 5);
        do_task(b, threadIdx.x & 31, tf, Wt1, bt1, Wt2, bt2, Wc1, bc1);
        return;
    }
    int e = bx * 256 + threadIdx.x;
    int i32 = block_detect_i32((const unsigned*)ei, bx * 256);
    int s, d;
    if (i32) { const int* p = (const int*)ei; s = p[e]; d = p[NE + e]; }
    else     { const long long* p = (const long long*)ei; s = (int)p[e]; d = (int)p[NE + e]; }
    int slot = atomicAdd(&g_cnt[d], 1);
    if (slot < CAP) g_ell[d * CAP + slot] = s;
}

// ---------------- 2) layer-1: warp per node, ELL gather of x, fused matvec ----------------
__global__ void __launch_bounds__(256) k_node1(
        const float* __restrict__ x,
        const float* __restrict__ Wl1, const float* __restrict__ bl1,
        const float* __restrict__ Wr1) {
    int n    = blockIdx.x * 8 + (threadIdx.x >> 5);
    int lane = threadIdx.x & 31;
    int deg  = min(g_cnt[n], CAP);
    const int* row = g_ell + n * CAP;
    float4 a = make_float4(0.f, 0.f, 0.f, 0.f);
    for (int e = lane; e < deg; e += 32) {
        float4 xv = __ldg((const float4*)(x + (size_t)row[e] * 4));
        a.x += xv.x; a.y += xv.y; a.z += xv.z; a.w += xv.w;
    }
#pragma unroll
    for (int off = 16; off; off >>= 1) {
        a.x += __shfl_xor_sync(0xffffffffu, a.x, off);
        a.y += __shfl_xor_sync(0xffffffffu, a.y, off);
        a.z += __shfl_xor_sync(0xffffffffu, a.z, off);
        a.w += __shfl_xor_sync(0xffffffffu, a.w, off);
    }
    float invd = 1.f / fmaxf((float)deg, 1.f);
    float m0 = a.x*invd, m1 = a.y*invd, m2 = a.z*invd, m3 = a.w*invd;
    float4 xn = __ldg((const float4*)(x + (size_t)n * 4));
    int oa = 2 * lane, ob = 2 * lane + 1;
    float va = bl1[oa]
             + Wl1[oa*4]*m0 + Wl1[oa*4+1]*m1 + Wl1[oa*4+2]*m2 + Wl1[oa*4+3]*m3
             + Wr1[oa*4]*xn.x + Wr1[oa*4+1]*xn.y + Wr1[oa*4+2]*xn.z + Wr1[oa*4+3]*xn.w;
    float vb = bl1[ob]
             + Wl1[ob*4]*m0 + Wl1[ob*4+1]*m1 + Wl1[ob*4+2]*m2 + Wl1[ob*4+3]*m3
             + Wr1[ob*4]*xn.x + Wr1[ob*4+1]*xn.y + Wr1[ob*4+2]*xn.z + Wr1[ob*4+3]*xn.w;
    va = fmaxf(va, 0.f); vb = fmaxf(vb, 0.f);
    *(float2*)(g_h1 + (size_t)n * 64 + oa) = make_float2(va, vb);
    g_h1h[n * 32 + lane] = __floats2half2_rn(va, vb);
}

// ---------------- 3) mean gather over fp16 h1: warp per node, int4 edges, 4 chains ----------------
__global__ void __launch_bounds__(256) k_gather2() {
    int n    = blockIdx.x * 8 + (threadIdx.x >> 5);
    int lane = threadIdx.x & 31;
    int deg  = min(g_cnt[n], CAP);
    const int4* row = (const int4*)(g_ell + n * CAP);
    float2 a = make_float2(0.f, 0.f), b = make_float2(0.f, 0.f);
    float2 c = make_float2(0.f, 0.f), d = make_float2(0.f, 0.f);
    int nq = deg >> 2;
    for (int q = 0; q < nq; q++) {
        int4 s4 = row[q];
        float2 va = __half22float2(__ldg(&g_h1h[s4.x * 32 + lane]));
        float2 vb = __half22float2(__ldg(&g_h1h[s4.y * 32 + lane]));
        float2 vc = __half22float2(__ldg(&g_h1h[s4.z * 32 + lane]));
        float2 vd = __half22float2(__ldg(&g_h1h[s4.w * 32 + lane]));
        a.x += va.x; a.y += va.y;
        b.x += vb.x; b.y += vb.y;
        c.x += vc.x; c.y += vc.y;
        d.x += vd.x; d.y += vd.y;
    }
    for (int e = nq * 4; e < deg; e++) {
        int s = g_ell[n * CAP + e];
        float2 v = __half22float2(__ldg(&g_h1h[s * 32 + lane]));
        a.x += v.x; a.y += v.y;
    }
    float invd = 1.f / fmaxf((float)deg, 1.f);
    float2 m;
    m.x = (a.x + b.x + c.x + d.x) * invd;
    m.y = (a.y + b.y + c.y + d.y) * invd;
    *(float2*)(g_mean + (size_t)n * 64 + 2 * lane) = m;
}

// ---------------- 4) GEMM with register tile 4 outs x 2 nodes (PROFILED) ----------------
// 128 threads = 16 out-groups x 8 node-pairs -> 16 nodes/block, grid 313.
// Inner k: 2x LDS.128 (wl,wr) + 2x LDS.64 (mean,x pairs) = 4 LDS per 16 FMA.
#define MM_NODES 16
#define MM_GRID  ((NN + MM_NODES - 1) / MM_NODES)    // 313
#define WS3 68                                       // float4-aligned weight stride
#define MS3 34                                       // float2-aligned feature stride
#define SM_BYTES ((3*64*WS3 + 2*64*MS3) * 4)         // 69632 B
__global__ void __launch_bounds__(128) k_l2mm(const float* __restrict__ Wl2,
                                              const float* __restrict__ bl2,
                                              const float* __restrict__ Wr2,
                                              const float* __restrict__ Wc1) {
    extern __shared__ float sm[];
    float* sWl   = sm;                   // [k*WS3 + o]
    float* sWr   = sm + 64*WS3;
    float* sWc   = sm + 2*64*WS3;
    float* sMean = sm + 3*64*WS3;        // [k*MS3 + nl]; aliased as sH2 later
    float* sX    = sMean + 64*MS3;
    int tid = threadIdx.x;
    int n0 = blockIdx.x * MM_NODES;

    for (int idx = tid; idx < 4096; idx += 128) {
        int o = idx >> 6, k = idx & 63;          // coalesced global reads
        sWl[k*WS3 + o] = Wl2[idx];
        sWr[k*WS3 + o] = Wr2[idx];
        sWc[k*WS3 + o] = Wc1[o*128 + k];         // h-part of Wc1
    }
    for (int idx = tid; idx < 1024; idx += 128) {
        int nl = idx >> 6, k = idx & 63;
        int n = n0 + nl;
        bool ok = (n < NN);
        sMean[k*MS3 + nl] = ok ? g_mean[n*64 + k] : 0.f;
        sX[k*MS3 + nl]    = ok ? g_h1[n*64 + k]   : 0.f;
    }
    __syncthreads();

    int tx = tid & 15, ny = tid >> 4;    // tx: out group (4 outs), ny: node pair (2 nodes)
    int o0 = tx * 4, nl0 = ny * 2;

    float4 bb = *(const float4*)(bl2 + o0);
    float4 accA = bb, accB = bb;         // nodes nl0, nl0+1
#pragma unroll
    for (int k = 0; k < 64; k++) {
        float2 m  = *(const float2*)(sMean + k*MS3 + nl0);
        float2 xv = *(const float2*)(sX + k*MS3 + nl0);
        float4 wl = *(const float4*)(sWl + k*WS3 + o0);
        float4 wr = *(const float4*)(sWr + k*WS3 + o0);
        accA.x += m.x*wl.x + xv.x*wr.x; accA.y += m.x*wl.y + xv.x*wr.y;
        accA.z += m.x*wl.z + xv.x*wr.z; accA.w += m.x*wl.w + xv.x*wr.w;
        accB.x += m.y*wl.x + xv.y*wr.x; accB.y += m.y*wl.y + xv.y*wr.y;
        accB.z += m.y*wl.z + xv.y*wr.z; accB.w += m.y*wl.w + xv.y*wr.w;
    }
    accA.x = fmaxf(accA.x, 0.f); accA.y = fmaxf(accA.y, 0.f);
    accA.z = fmaxf(accA.z, 0.f); accA.w = fmaxf(accA.w, 0.f);
    accB.x = fmaxf(accB.x, 0.f); accB.y = fmaxf(accB.y, 0.f);
    accB.z = fmaxf(accB.z, 0.f); accB.w = fmaxf(accB.w, 0.f);
    __syncthreads();                     // all sMean/sX reads complete

    float* sH2 = sMean;                  // alias: [o*MS3 + nl]
    sH2[(o0+0)*MS3 + nl0]   = accA.x; sH2[(o0+1)*MS3 + nl0]   = accA.y;
    sH2[(o0+2)*MS3 + nl0]   = accA.z; sH2[(o0+3)*MS3 + nl0]   = accA.w;
    sH2[(o0+0)*MS3 + nl0+1] = accB.x; sH2[(o0+1)*MS3 + nl0+1] = accB.y;
    sH2[(o0+2)*MS3 + nl0+1] = accB.z; sH2[(o0+3)*MS3 + nl0+1] = accB.w;
    __syncthreads();

    float4 pA = make_float4(0.f,0.f,0.f,0.f), pB = make_float4(0.f,0.f,0.f,0.f);
#pragma unroll
    for (int k = 0; k < 64; k++) {
        float2 h2 = *(const float2*)(sH2 + k*MS3 + nl0);
        float4 wc = *(const float4*)(sWc + k*WS3 + o0);
        pA.x += h2.x*wc.x; pA.y += h2.x*wc.y; pA.z += h2.x*wc.z; pA.w += h2.x*wc.w;
        pB.x += h2.y*wc.x; pB.y += h2.y*wc.y; pB.z += h2.y*wc.z; pB.w += h2.y*wc.w;
    }
    int n = n0 + nl0;
    if (n < NN)     *(float4*)(g_hp + (size_t)n * 64 + o0)       = pA;
    if (n + 1 < NN) *(float4*)(g_hp + (size_t)(n + 1) * 64 + o0) = pB;
}

// ---------------- 5) final scores + re-zero side job ----------------
// Tile 128 nodes x 64 batches, 256 threads, grid (40,8).
#define FIN_SMEM (64*129*4 + 64*64*4 + 64*8)
__global__ void __launch_bounds__(256) k_final(const float* __restrict__ Wc2,
                                               const float* __restrict__ bc2,
                                               float* __restrict__ out) {
    extern __shared__ float smf[];
    float* s_hp = smf;                         // [h][r], stride 129
    float* s_tp = smf + 64 * 129;              // [h][b], 64 wide
    unsigned long long* s_w2 = (unsigned long long*)(smf + 64 * 129 + 64 * 64);
    int tid = threadIdx.x;

    // side job: re-zero degree counters (blocks 0..19 x 256 = 5120 >= 5000)
    int bid = blockIdx.y * gridDim.x + blockIdx.x;
    if (bid < 20) {
        int i = bid * 256 + tid;
        if (i < NN) g_cnt[i] = 0;
    }

    int n0 = blockIdx.x * 128, b0 = blockIdx.y * 64;
    for (int idx = tid; idx < 8192; idx += 256) {
        int r = idx >> 6, h = idx & 63;
        s_hp[h*129 + r] = g_hp[(size_t)(n0 + r) * 64 + h];
    }
    for (int idx = tid; idx < 4096; idx += 256) {
        int h = idx >> 6, b = idx & 63;
        s_tp[h*64 + b] = g_tpT[h * BATCH + b0 + b];
    }
    if (tid < 64) { float w = Wc2[tid]; s_w2[tid] = pack2(w, w); }
    __syncthreads();

    int nla = tid & 63, q = tid >> 6;          // q in {0..3}: 16 batches each
    int nlb = nla + 64;
    U64 accA[8], accB[8];
#pragma unroll
    for (int p = 0; p < 8; p++) { accA[p].u = 0ull; accB[p].u = 0ull; }

#pragma unroll 4
    for (int h = 0; h < 64; h++) {
        float hva = s_hp[h*129 + nla];
        float hvb = s_hp[h*129 + nlb];
        unsigned long long ha = pack2(hva, hva);
        unsigned long long hb = pack2(hvb, hvb);
        unsigned long long w2 = s_w2[h];
        const unsigned long long* tp = (const unsigned long long*)(s_tp + h*64 + q*16);
#pragma unroll
        for (int p = 0; p < 8; p++) {
            unsigned long long t2 = tp[p];
            U64 a, b;
            asm("add.rn.f32x2 %0, %1, %2;" : "=l"(a.u) : "l"(t2), "l"(ha));
            asm("add.rn.f32x2 %0, %1, %2;" : "=l"(b.u) : "l"(t2), "l"(hb));
            a.f.x = fmaxf(a.f.x, 0.f); a.f.y = fmaxf(a.f.y, 0.f);
            b.f.x = fmaxf(b.f.x, 0.f); b.f.y = fmaxf(b.f.y, 0.f);
            asm("fma.rn.f32x2 %0, %1, %2, %0;" : "+l"(accA[p].u) : "l"(a.u), "l"(w2));
            asm("fma.rn.f32x2 %0, %1, %2, %0;" : "+l"(accB[p].u) : "l"(b.u), "l"(w2));
        }
    }

    float bias = bc2[0];
    int na = n0 + nla, nb = n0 + nlb;
    if (na < NN) {
#pragma unroll
        for (int p = 0; p < 8; p++) {
            int b = b0 + q*16 + 2*p;
            out[(size_t)b       * NN + na] = accA[p].f.x + bias;
            out[(size_t)(b + 1) * NN + na] = accA[p].f.y + bias;
        }
    }
    if (nb < NN) {
#pragma unroll
        for (int p = 0; p < 8; p++) {
            int b = b0 + q*16 + 2*p;
            out[(size_t)b       * NN + nb] = accB[p].f.x + bias;
            out[(size_t)(b + 1) * NN + nb] = accB[p].f.y + bias;
        }
    }
}

// ---------------- launch ----------------
extern "C" void kernel_launch(void* const* d_in, const int* in_sizes, int n_in,
                              void* d_out, int out_size) {
    const float* x   = (const float*)d_in[0];
    const void*  ei  = d_in[1];
    const float* tf  = (const float*)d_in[2];
    const float* Wl1 = (const float*)d_in[3];
    const float* bl1 = (const float*)d_in[4];
    const float* Wr1 = (const float*)d_in[5];
    const float* Wl2 = (const float*)d_in[6];
    const float* bl2 = (const float*)d_in[7];
    const float* Wr2 = (const float*)d_in[8];
    const float* Wt1 = (const float*)d_in[9];
    const float* bt1 = (const float*)d_in[10];
    const float* Wt2 = (const float*)d_in[11];
    const float* bt2 = (const float*)d_in[12];
    const float* Wc1 = (const float*)d_in[13];
    const float* bc1 = (const float*)d_in[14];
    const float* Wc2 = (const float*)d_in[15];
    const float* bc2 = (const float*)d_in[16];
    float* out = (float*)d_out;

    static bool attr_set = false;
    if (!attr_set) {
        cudaFuncSetAttribute(k_l2mm,  cudaFuncAttributeMaxDynamicSharedMemorySize, SM_BYTES);
        cudaFuncSetAttribute(k_final, cudaFuncAttributeMaxDynamicSharedMemorySize, FIN_SMEM);
        attr_set = true;
    }

    k_edge   <<<689, 256>>>(ei, tf, Wt1, bt1, Wt2, bt2, Wc1, bc1);
    k_node1  <<<625, 256>>>(x, Wl1, bl1, Wr1);
    k_gather2<<<625, 256>>>();
    k_l2mm   <<<MM_GRID, 128, SM_BYTES>>>(Wl2, bl2, Wr2, Wc1);   // 4th -> profiled
    k_final  <<<dim3(40, 8), 256, FIN_SMEM>>>(Wc2, bc2, out);
}